// round 3
// baseline (speedup 1.0000x reference)
#include <cuda_runtime.h>
#include <cuda_bf16.h>

// AUCM loss: mean over (pos, neg) pairs of (1 - (p_i - n_j))^2 + relu(1 - (p_i - n_j))
// Strategy: compact pos/neg into device scratch, brute-force Np x Nn pair tile
// (only ~18.5M pairs vs 268M in the reference's full N^2), double-precision
// cross-block reduction, tiny finalize kernel. All graph-capturable, no allocs.

#define NMAX 16384
#define PB   128      // positives per block (= threads per block in pair kernel)
#define NEG_SPLITS 16 // blocks along the negative axis
#define NEG_TILE 1024 // negatives staged in shared per iteration

__device__ float  g_pos[NMAX];
__device__ float  g_neg[NMAX];
__device__ int    g_np;
__device__ int    g_nn;
__device__ double g_sum;

__global__ void init_kernel() {
    g_np = 0;
    g_nn = 0;
    g_sum = 0.0;
}

__global__ void compact_kernel(const float* __restrict__ preds,
                               const int* __restrict__ targets,
                               int n) {
    int i = blockIdx.x * blockDim.x + threadIdx.x;
    int stride = gridDim.x * blockDim.x;
    for (; i < n; i += stride) {
        float p = preds[i];
        if (targets[i] == 1) {
            int k = atomicAdd(&g_np, 1);
            g_pos[k] = 1.0f - p;        // a_i = 1 - p_i
        } else {
            int k = atomicAdd(&g_nn, 1);
            g_neg[k] = p;               // b_j = n_j
        }
    }
}

__global__ void __launch_bounds__(PB) pair_kernel() {
    const int np = g_np;
    const int nn = g_nn;

    const int p0 = blockIdx.x * PB;
    if (p0 >= np) return;   // uniform per block: safe early exit

    __shared__ float sb[NEG_TILE];
    __shared__ double red[PB];

    const int tid = threadIdx.x;
    const bool valid = (p0 + tid) < np;
    const float a = valid ? g_pos[p0 + tid] : 0.0f;

    // This block's negative range
    const int chunk = (nn + NEG_SPLITS - 1) / NEG_SPLITS;
    const int nbeg = blockIdx.y * chunk;
    const int nend = min(nbeg + chunk, nn);

    float s = 0.0f;
    for (int base = nbeg; base < nend; base += NEG_TILE) {
        const int cnt = min(NEG_TILE, nend - base);
        for (int j = tid; j < cnt; j += PB)
            sb[j] = g_neg[base + j];
        __syncthreads();

        if (valid) {
            int j = 0;
            // main unrolled loop
            #pragma unroll 4
            for (; j + 4 <= cnt; j += 4) {
                float d0 = a + sb[j + 0];
                float d1 = a + sb[j + 1];
                float d2 = a + sb[j + 2];
                float d3 = a + sb[j + 3];
                s += fmaf(d0, d0, fmaxf(d0, 0.0f));
                s += fmaf(d1, d1, fmaxf(d1, 0.0f));
                s += fmaf(d2, d2, fmaxf(d2, 0.0f));
                s += fmaf(d3, d3, fmaxf(d3, 0.0f));
            }
            for (; j < cnt; ++j) {
                float d = a + sb[j];
                s += fmaf(d, d, fmaxf(d, 0.0f));
            }
        }
        __syncthreads();
    }

    // Block reduction in double, then one double atomic per block
    red[tid] = (double)s;
    __syncthreads();
    for (int off = PB / 2; off > 0; off >>= 1) {
        if (tid < off) red[tid] += red[tid + off];
        __syncthreads();
    }
    if (tid == 0) atomicAdd(&g_sum, red[0]);
}

__global__ void finalize_kernel(float* __restrict__ out) {
    double denom = (double)g_np * (double)g_nn;
    out[0] = (float)(g_sum / denom);
}

extern "C" void kernel_launch(void* const* d_in, const int* in_sizes, int n_in,
                              void* d_out, int out_size) {
    const float* preds   = (const float*)d_in[0];
    const int*   targets = (const int*)d_in[1];
    float*       out     = (float*)d_out;
    const int n = in_sizes[0];

    init_kernel<<<1, 1>>>();
    compact_kernel<<<64, 256>>>(preds, targets, n);

    dim3 grid((n + PB - 1) / PB, NEG_SPLITS);
    pair_kernel<<<grid, PB>>>();

    finalize_kernel<<<1, 1>>>(out);
}